// round 11
// baseline (speedup 1.0000x reference)
#include <cuda_runtime.h>
#include <math.h>

// x: (B=4, S=128, H=128, W=128) fp32 ; ada_mask: (B, S, K=21) fp32
// out[b,s,h,w] = sum_k softmax(ada_mask[b,s,:])[k] * xpad[b, s+k-10, h, w]
#define B_DIM    4
#define S_DIM    128
#define HW2_DIM  8192                  // H*W / 2 (float2 pixels per plane)
#define K_DIM    21
#define PAD      10
#define TILE_S   16                    // output rows (s) per thread
#define THREADS  128
#define WROW     44                    // duplicated weight row: 21 (w,w) pairs + pad pair
#define WIN      (TILE_S + K_DIM - 1)  // 36 planes, ALL loaded upfront (proven best)

typedef unsigned long long u64;

// Packed 2-wide fp32 FMA / ADD (Blackwell f32x2) — one instr, two fp32 lanes.
__device__ __forceinline__ u64 fma2(u64 a, u64 b, u64 c) {
    u64 d;
    asm("fma.rn.f32x2 %0, %1, %2, %3;" : "=l"(d) : "l"(a), "l"(b), "l"(c));
    return d;
}
__device__ __forceinline__ u64 add2(u64 a, u64 b) {
    u64 d;
    asm("add.rn.f32x2 %0, %1, %2;" : "=l"(d) : "l"(a), "l"(b));
    return d;
}

__global__ __launch_bounds__(THREADS, 5)
void AdaptiveMixing_28784870818046_kernel(const u64*   __restrict__ x,
                                          const float* __restrict__ ada_mask,
                                          u64*         __restrict__ out)
{
    // duplicated softmax weights: row j holds pairs (w_k, w_k), k = 0..20; pair 21 = pad
    __shared__ __align__(16) float ws[TILE_S * WROW];

    const int b  = blockIdx.z;
    const int s0 = blockIdx.y * TILE_S;
    const int p  = blockIdx.x * THREADS + threadIdx.x;   // float2-pixel idx [0, HW2)

    // ---- per-(b,s) softmax over K=21 for rows s0..s0+15, stored duplicated ----
    if (threadIdx.x < TILE_S) {
        const int s = s0 + threadIdx.x;
        const float* m = ada_mask + ((size_t)b * S_DIM + s) * K_DIM;
        float mv[K_DIM];
        float mx = -3.402823466e+38f;
        #pragma unroll
        for (int k = 0; k < K_DIM; ++k) { mv[k] = m[k]; mx = fmaxf(mx, mv[k]); }
        float sum = 0.f;
        #pragma unroll
        for (int k = 0; k < K_DIM; ++k) { mv[k] = expf(mv[k] - mx); sum += mv[k]; }
        const float inv = 1.0f / sum;
        float* row = ws + threadIdx.x * WROW;
        #pragma unroll
        for (int k = 0; k < K_DIM; ++k) {
            const float w = mv[k] * inv;
            row[2 * k]     = w;
            row[2 * k + 1] = w;
        }
        row[42] = 0.f;   // pad pair
        row[43] = 0.f;
    }
    __syncthreads();

    const u64* xb = x + (size_t)b * S_DIM * HW2_DIM + p;
    u64*       ob = out + ((size_t)b * S_DIM + s0) * HW2_DIM + p;

    // ---- upfront batched load of the full 36-plane float2 window ----
    // (single exposed latency for the whole tile; max MLP; all values live)
    u64 win[WIN];
    #pragma unroll
    for (int i = 0; i < WIN; ++i) {
        const int s = s0 - PAD + i;
        win[i] = (s >= 0 && s < S_DIM) ? xb[(size_t)s * HW2_DIM] : 0ULL;
    }

    // ---- 16 compute-only rows: 11 LDS + 21 fma2 + 1 add2 + 1 STG each ----
    #pragma unroll
    for (int j = 0; j < TILE_S; ++j) {
        const float* row = ws + j * WROW;
        u64 a = 0ULL, c = 0ULL;                      // 2 accumulation chains

        #pragma unroll
        for (int q = 0; q < 10; ++q) {               // k = 0..19 (pairs via LDS.128)
            const ulonglong2 wp = reinterpret_cast<const ulonglong2*>(row)[q];
            a = fma2(wp.x, win[j + 2 * q],     a);
            c = fma2(wp.y, win[j + 2 * q + 1], c);
        }
        // k = 20 singleton (duplicated pair at float-offset 40)
        a = fma2(reinterpret_cast<const u64*>(row)[20], win[j + 20], a);

        ob[(size_t)j * HW2_DIM] = add2(a, c);
    }
}

extern "C" void kernel_launch(void* const* d_in, const int* in_sizes, int n_in,
                              void* d_out, int out_size)
{
    const u64* x          = (const u64*)d_in[0];     // (4,128,128,128) fp32 as float2
    const float* ada_mask = (const float*)d_in[1];   // (4,128,21) fp32
    u64* out              = (u64*)d_out;

    dim3 grid(HW2_DIM / THREADS,   // 64 pixel-blocks
              S_DIM / TILE_S,      // 8 s-tiles
              B_DIM);              // 4 batches
    AdaptiveMixing_28784870818046_kernel<<<grid, THREADS>>>(x, ada_mask, out);
}

// round 13
// speedup vs baseline: 1.1404x; 1.1404x over previous
#include <cuda_runtime.h>
#include <math.h>

// x: (B=4, S=128, H=128, W=128) fp32 ; ada_mask: (B, S, K=21) fp32
// out[b,s,h,w] = sum_k softmax(ada_mask[b,s,:])[k] * xpad[b, s+k-10, h, w]
#define B_DIM    4
#define S_DIM    128
#define HW2_DIM  8192                  // H*W / 2 (float2 pixels per plane)
#define K_DIM    21
#define PAD      10
#define TILE_S   32                    // s-rows per CTA (2 chained chunks of 16)
#define CHUNK    16
#define THREADS  128
#define WROW     22                    // weight row: 21 weights + 1 pad float
#define WIN_TOT  (TILE_S + K_DIM - 1)  // 52 planes total; peak live ~36 (chunks share 20)

__global__ __launch_bounds__(THREADS, 5)
void AdaptiveMixing_28784870818046_kernel(const float2* __restrict__ x,
                                          const float*  __restrict__ ada_mask,
                                          float2* __restrict__ out)
{
    __shared__ __align__(16) float ws[TILE_S * WROW + 2];  // +2: float4 reads in-bounds

    const int b  = blockIdx.z;
    const int s0 = blockIdx.y * TILE_S;
    const int p  = blockIdx.x * THREADS + threadIdx.x;   // float2-pixel idx [0, HW2)

    const float2* xb = x + (size_t)b * S_DIM * HW2_DIM + p;
    float2*       ob = out + ((size_t)b * S_DIM + s0) * HW2_DIM + p;

    // ---- chunk-0 window: planes 0..35 (s = s0-10+i), issued BEFORE softmax/bar
    //      so the L2 latency overlaps the weight computation ----
    float2 win[WIN_TOT];
    #pragma unroll
    for (int i = 0; i < CHUNK + K_DIM - 1; ++i) {        // 36 planes
        const int s = s0 - PAD + i;
        win[i] = (s >= 0 && s < S_DIM) ? xb[(size_t)s * HW2_DIM]
                                       : make_float2(0.f, 0.f);
    }

    // ---- per-(b,s) softmax over K=21 for all 32 rows of this CTA ----
    if (threadIdx.x < TILE_S) {
        const int s = s0 + threadIdx.x;
        const float* m = ada_mask + ((size_t)b * S_DIM + s) * K_DIM;
        float mv[K_DIM];
        float mx = -3.402823466e+38f;
        #pragma unroll
        for (int k = 0; k < K_DIM; ++k) { mv[k] = m[k]; mx = fmaxf(mx, mv[k]); }
        float sum = 0.f;
        #pragma unroll
        for (int k = 0; k < K_DIM; ++k) { mv[k] = expf(mv[k] - mx); sum += mv[k]; }
        const float inv = 1.0f / sum;
        float* row = ws + threadIdx.x * WROW;
        #pragma unroll
        for (int k = 0; k < K_DIM; ++k) row[k] = mv[k] * inv;
        row[21] = 0.f;
    }
    __syncthreads();

    // ---- chunk 0: rows 0..15 (consume win[j .. j+20]) ----
    #pragma unroll
    for (int j = 0; j < CHUNK; ++j) {
        const float* row = ws + j * WROW;
        float a0x = 0.f, a0y = 0.f, a1x = 0.f, a1y = 0.f;
        #pragma unroll
        for (int q = 0; q < 5; ++q) {                    // k = 0..19 via float4 LDS
            const float4 w4 = reinterpret_cast<const float4*>(row)[q];
            const float2 v0 = win[j + 4*q + 0];
            const float2 v1 = win[j + 4*q + 1];
            const float2 v2 = win[j + 4*q + 2];
            const float2 v3 = win[j + 4*q + 3];
            a0x = fmaf(w4.x, v0.x, a0x);  a0y = fmaf(w4.x, v0.y, a0y);
            a1x = fmaf(w4.y, v1.x, a1x);  a1y = fmaf(w4.y, v1.y, a1y);
            a0x = fmaf(w4.z, v2.x, a0x);  a0y = fmaf(w4.z, v2.y, a0y);
            a1x = fmaf(w4.w, v3.x, a1x);  a1y = fmaf(w4.w, v3.y, a1y);
        }
        {
            const float w20 = row[20];                   // k = 20 singleton
            const float2 v = win[j + 20];
            a0x = fmaf(w20, v.x, a0x);    a0y = fmaf(w20, v.y, a0y);
        }
        float2 r;  r.x = a0x + a1x;  r.y = a0y + a1y;
        ob[(size_t)j * HW2_DIM] = r;
    }

    // ---- chunk-1 window: 16 NEW planes 36..51 (s = s0+26 .. s0+41, only top clip);
    //      planes 16..35 (20 overlap) stay live in registers ----
    #pragma unroll
    for (int i = CHUNK + K_DIM - 1; i < WIN_TOT; ++i) {
        const int s = s0 - PAD + i;
        win[i] = (s < S_DIM) ? xb[(size_t)s * HW2_DIM] : make_float2(0.f, 0.f);
    }

    // ---- chunk 1: rows 16..31 ----
    #pragma unroll
    for (int j = CHUNK; j < TILE_S; ++j) {
        const float* row = ws + j * WROW;
        float a0x = 0.f, a0y = 0.f, a1x = 0.f, a1y = 0.f;
        #pragma unroll
        for (int q = 0; q < 5; ++q) {
            const float4 w4 = reinterpret_cast<const float4*>(row)[q];
            const float2 v0 = win[j + 4*q + 0];
            const float2 v1 = win[j + 4*q + 1];
            const float2 v2 = win[j + 4*q + 2];
            const float2 v3 = win[j + 4*q + 3];
            a0x = fmaf(w4.x, v0.x, a0x);  a0y = fmaf(w4.x, v0.y, a0y);
            a1x = fmaf(w4.y, v1.x, a1x);  a1y = fmaf(w4.y, v1.y, a1y);
            a0x = fmaf(w4.z, v2.x, a0x);  a0y = fmaf(w4.z, v2.y, a0y);
            a1x = fmaf(w4.w, v3.x, a1x);  a1y = fmaf(w4.w, v3.y, a1y);
        }
        {
            const float w20 = row[20];
            const float2 v = win[j + 20];
            a0x = fmaf(w20, v.x, a0x);    a0y = fmaf(w20, v.y, a0y);
        }
        float2 r;  r.x = a0x + a1x;  r.y = a0y + a1y;
        ob[(size_t)j * HW2_DIM] = r;
    }
}

extern "C" void kernel_launch(void* const* d_in, const int* in_sizes, int n_in,
                              void* d_out, int out_size)
{
    const float2* x       = (const float2*)d_in[0];   // (4,128,128,128) fp32 as float2
    const float* ada_mask = (const float*)d_in[1];    // (4,128,21) fp32
    float2* out           = (float2*)d_out;

    dim3 grid(HW2_DIM / THREADS,   // 64 pixel-blocks
              S_DIM / TILE_S,      // 4 s-groups
              B_DIM);              // 4 batches  => 1024 CTAs
    AdaptiveMixing_28784870818046_kernel<<<grid, THREADS>>>(x, ada_mask, out);
}